// round 5
// baseline (speedup 1.0000x reference)
#include <cuda_runtime.h>
#include <cstdint>

#define NB      32
#define NCH     84
#define NCLS    80
#define NANCH   8400
#define NQUAD   2100          // NANCH / 4
#define TOPK    1000
#define MAXDET  300
#define CONF    0.25f
#define IOU_THR 0.7f
#define MAX_WH  7680.0f
#define IMG_SZ  640.0f

// ---------------- scratch (device globals; no allocation allowed) ----------
__device__ unsigned long long g_key  [NB * NANCH];   // (fmap(score)<<32)|~idx
__device__ int                g_label[NB * NANCH];
__device__ float              g_box  [NB * NANCH * 4];
__device__ float              g_top_score[NB * TOPK];
__device__ int                g_top_label[NB * TOPK];
__device__ float              g_top_box  [NB * TOPK * 4];
// transposed suppression matrix, word-major: supT[b][w][r] bit bb = i=w*64+bb
// suppresses r (i < r, iou > 0.7).
__device__ unsigned long long g_supT[(size_t)NB * 16 * TOPK];

__constant__ int c_coco[80] = {
    1,2,3,4,5,6,7,8,9,10,11,13,14,15,16,17,18,19,20,21,22,23,24,25,27,28,
    31,32,33,34,35,36,37,38,39,40,41,42,43,44,46,47,48,49,50,51,52,53,54,55,
    56,57,58,59,60,61,62,63,64,65,67,70,72,73,74,75,76,77,78,79,80,81,82,84,
    85,86,87,88,89,90
};

__device__ __forceinline__ unsigned int fmap(float f) {
    unsigned int u = __float_as_uint(f);
    return (u & 0x80000000u) ? ~u : (u | 0x80000000u);
}
__device__ __forceinline__ float funmap(unsigned int u) {
    return (u & 0x80000000u) ? __uint_as_float(u ^ 0x80000000u)
                             : __uint_as_float(~u);
}

// ---------------- stage 1: decode (float4, 4 anchors/thread) ---------------
// preds [32, 84, 8400]; thread handles anchors 4g..4g+3 via 84 independent
// LDG.128s. Per-component strict-> argmax == jnp.argmax (first max index).
__global__ void __launch_bounds__(256) decode_kernel(const float4* __restrict__ p4) {
    int g = blockIdx.x * blockDim.x + threadIdx.x;
    int b = blockIdx.y;
    if (g >= NQUAD) return;
    const float4* base = p4 + (size_t)b * (NCH * NQUAD) + g;

    float4 vx = base[0];
    float4 vy = base[NQUAD];
    float4 vw = base[2 * NQUAD];
    float4 vh = base[3 * NQUAD];

    float4 best = base[4 * NQUAD];
    int4   bi   = make_int4(0, 0, 0, 0);
#pragma unroll 16
    for (int c = 1; c < NCLS; c++) {
        float4 v = base[(4 + c) * NQUAD];
        if (v.x > best.x) { best.x = v.x; bi.x = c; }
        if (v.y > best.y) { best.y = v.y; bi.y = c; }
        if (v.z > best.z) { best.z = v.z; bi.z = c; }
        if (v.w > best.w) { best.w = v.w; bi.w = c; }
    }

    int o = b * NANCH + 4 * g;

    float s0 = (best.x > CONF) ? best.x : -1.0f;
    float s1 = (best.y > CONF) ? best.y : -1.0f;
    float s2 = (best.z > CONF) ? best.z : -1.0f;
    float s3 = (best.w > CONF) ? best.w : -1.0f;

    unsigned long long k0 = ((unsigned long long)fmap(s0) << 32) | (unsigned int)(~(4*g+0));
    unsigned long long k1 = ((unsigned long long)fmap(s1) << 32) | (unsigned int)(~(4*g+1));
    unsigned long long k2 = ((unsigned long long)fmap(s2) << 32) | (unsigned int)(~(4*g+2));
    unsigned long long k3 = ((unsigned long long)fmap(s3) << 32) | (unsigned int)(~(4*g+3));
    ((ulonglong2*)g_key)[o/2]     = make_ulonglong2(k0, k1);
    ((ulonglong2*)g_key)[o/2 + 1] = make_ulonglong2(k2, k3);

    ((int4*)g_label)[b * NQUAD + g] = bi;

    float4* boxo = (float4*)g_box + o;
    {
        float x = vx.x * IMG_SZ, y = vy.x * IMG_SZ, hw = vw.x * IMG_SZ * 0.5f, hh = vh.x * IMG_SZ * 0.5f;
        boxo[0] = make_float4(x - hw, y - hh, x + hw, y + hh);
    }
    {
        float x = vx.y * IMG_SZ, y = vy.y * IMG_SZ, hw = vw.y * IMG_SZ * 0.5f, hh = vh.y * IMG_SZ * 0.5f;
        boxo[1] = make_float4(x - hw, y - hh, x + hw, y + hh);
    }
    {
        float x = vx.z * IMG_SZ, y = vy.z * IMG_SZ, hw = vw.z * IMG_SZ * 0.5f, hh = vh.z * IMG_SZ * 0.5f;
        boxo[2] = make_float4(x - hw, y - hh, x + hw, y + hh);
    }
    {
        float x = vx.w * IMG_SZ, y = vy.w * IMG_SZ, hw = vw.w * IMG_SZ * 0.5f, hh = vh.w * IMG_SZ * 0.5f;
        boxo[3] = make_float4(x - hw, y - hh, x + hw, y + hh);
    }
}

// ---------------- stage 2: exact top-1000 via radix select + 1K sort -------
#define SEL_SMEM ((8448 + 1024) * 8)

__global__ void __launch_bounds__(1024) select_kernel() {
    extern __shared__ unsigned long long sm[];
    unsigned long long* key  = sm;          // 8400 (8448 pad)
    unsigned long long* cand = sm + 8448;   // 1024
    __shared__ int hist[256];
    __shared__ unsigned long long s_prefix;
    __shared__ int s_k, s_cnt;

    int b = blockIdx.x, tid = threadIdx.x;
    int lane = tid & 31;

    for (int i = tid; i < NANCH; i += 1024)
        key[i] = g_key[b * NANCH + i];
    if (tid == 0) { s_prefix = 0ull; s_k = TOPK; s_cnt = 0; }
    __syncthreads();

    const int shifts[6] = {56, 48, 40, 32, 8, 0};
#pragma unroll 1
    for (int pass = 0; pass < 6; ++pass) {
        if (tid < 256) hist[tid] = 0;
        __syncthreads();
        unsigned long long pfx = s_prefix;
        int shift = shifts[pass];
#pragma unroll 1
        for (int ii = 0; ii < 9; ++ii) {
            int i = tid + ii * 1024;
            unsigned long long v = (i < NANCH) ? key[i] : 0ull;
            bool act = (i < NANCH) &&
                       ((pass == 0) || ((v >> (shift + 8)) == pfx));
            int bin = act ? (int)((v >> shift) & 255ull) : (300 + lane);
            unsigned grp = __match_any_sync(0xFFFFFFFFu, bin);
            if (act && lane == (__ffs(grp) - 1))
                atomicAdd(&hist[bin], __popc(grp));
        }
        __syncthreads();
        if (tid == 0) {
            int k = s_k, d = 255;
            for (;; --d) { int h = hist[d]; if (h >= k) break; k -= h; }
            unsigned long long np = (pfx << 8) | (unsigned long long)d;
            if (pass == 3) np = (np << 16) | 0xFFFFull;   // ~idx high bits known
            s_prefix = np;
            s_k = k;
        }
        __syncthreads();
    }

    unsigned long long thr = s_prefix;    // exact 1000th-largest key
    for (int i = tid; i < NANCH; i += 1024) {
        unsigned long long v = key[i];
        if (v >= thr) { int p = atomicAdd(&s_cnt, 1); cand[p] = v; }
    }
    __syncthreads();
    if (tid < 1024 - TOPK) cand[TOPK + tid] = 0ull;
    __syncthreads();

    for (int kk = 2; kk <= 1024; kk <<= 1) {
        for (int j = kk >> 1; j > 0; j >>= 1) {
            if (tid < 512) {
                int i = ((tid & ~(j - 1)) << 1) | (tid & (j - 1));
                int l = i | j;
                unsigned long long a = cand[i], c = cand[l];
                bool desc = ((i & kk) == 0);
                if (desc ? (a < c) : (a > c)) { cand[i] = c; cand[l] = a; }
            }
            __syncthreads();
        }
    }

    if (tid < TOPK) {
        unsigned long long kv = cand[tid];
        unsigned int idx = ~(unsigned int)(kv & 0xFFFFFFFFull);
        int src = b * NANCH + (int)idx;
        int o   = b * TOPK + tid;
        g_top_score[o] = funmap((unsigned int)(kv >> 32));  // exact round-trip
        g_top_label[o] = g_label[src];
        ((float4*)g_top_box)[o] = ((const float4*)g_box)[src];
    }
}

// ---------------- stage 3a: transposed suppression bitmatrix ---------------
// Division-free interval test (bit-exact vs reference divide-then-compare;
// exact division fallback inside the +/-1e-6 band). 5 slices x 32 = 160 CTAs.
#define NSLICE 5
__global__ void __launch_bounds__(1024) supbuild_kernel() {
    __shared__ float sx1[TOPK], sy1[TOPK], sx2[TOPK], sy2[TOPK], sar[TOPK];
    int b = blockIdx.y, slice = blockIdx.x, tid = threadIdx.x;
    const int ROWS_PER = TOPK / NSLICE;   // 200

    for (int t = tid; t < TOPK; t += 1024) {
        int o = b * TOPK + t;
        float off = (float)g_top_label[o] * MAX_WH;
        float4 bx = ((const float4*)g_top_box)[o];
        float a0 = bx.x + off, a1 = bx.y + off, a2 = bx.z + off, a3 = bx.w + off;
        sx1[t] = a0; sy1[t] = a1; sx2[t] = a2; sy2[t] = a3;
        sar[t] = (a2 - a0) * (a3 - a1);
    }
    __syncthreads();

    const float HI = 0.7000007f;
    const float LO = 0.6999993f;

    for (int t = tid; t < ROWS_PER * 16; t += 1024) {
        int r = slice * ROWS_PER + (t % ROWS_PER);
        int w = t / ROWS_PER;
        int j0 = w * 64;
        size_t dst = ((size_t)b * 16 + w) * TOPK + r;
        if (j0 >= r) { g_supT[dst] = 0ull; continue; }

        float bx1 = sx1[r], by1 = sy1[r], bx2 = sx2[r], by2 = sy2[r], ba = sar[r];
        unsigned long long m = 0;
        int nbb = min(64, r - j0);
#pragma unroll 4
        for (int bb = 0; bb < nbb; ++bb) {
            int i = j0 + bb;
            float lx = fmaxf(bx1, sx1[i]);
            float ly = fmaxf(by1, sy1[i]);
            float rx = fminf(bx2, sx2[i]);
            float ry = fminf(by2, sy2[i]);
            float wd = fmaxf(rx - lx, 0.0f);
            float ht = fmaxf(ry - ly, 0.0f);
            float inter = wd * ht;
            float denom = ba + sar[i] - inter + 1e-7f;
            bool sup;
            if (inter > HI * denom)       sup = true;
            else if (inter < LO * denom)  sup = false;
            else                          sup = (inter / denom) > IOU_THR;
            if (sup) m |= (1ull << bb);
        }
        g_supT[dst] = m;
    }
}

// ---------------- stage 3b: Jacobi-fixpoint resolve + compact + emit --------
__global__ void __launch_bounds__(1024) resolve_kernel(float* __restrict__ out) {
    __shared__ unsigned long long kbuf[2][16];
    __shared__ int s_changed;

    int b = blockIdx.x, tid = threadIdx.x;
    int wid = tid >> 5, lane = tid & 31;

    float* ob = out + (size_t)b * MAXDET * 4;
    float* os = out + (size_t)NB * MAXDET * 4 + (size_t)b * MAXDET;
    float* ol = out + (size_t)NB * MAXDET * 5 + (size_t)b * MAXDET;

    for (int t = tid; t < MAXDET; t += 1024) {
        ((float4*)ob)[t] = make_float4(0.f, 0.f, 0.f, 0.f);
        os[t] = 0.0f;
        ol[t] = 0.0f;
    }

    unsigned long long r[16];
    const unsigned long long* gs = g_supT + (size_t)b * 16 * TOPK;
#pragma unroll
    for (int w = 0; w < 16; ++w)
        r[w] = (tid < TOPK) ? gs[w * TOPK + tid] : 0ull;

    if (tid == 0) s_changed = 0;
    if (tid < 32) ((unsigned int*)kbuf[0])[tid] = 0xFFFFFFFFu;
    __syncthreads();

    int cur = 0;
#pragma unroll 1
    for (int it = 0; it < 1001; ++it) {
        bool suppressed = false;
#pragma unroll
        for (int w = 0; w < 16; ++w)
            suppressed |= (r[w] & kbuf[cur][w]) != 0ull;
        unsigned bal = __ballot_sync(0xFFFFFFFFu, !suppressed);
        if (lane == 0) {
            unsigned old = ((unsigned int*)kbuf[cur])[wid];
            ((unsigned int*)kbuf[cur ^ 1])[wid] = bal;
            if (bal != old) s_changed = 1;
        }
        __syncthreads();
        int ch = s_changed;
        __syncthreads();
        if (!ch) break;
        if (tid == 0) s_changed = 0;
        cur ^= 1;
        __syncthreads();
    }

    __shared__ int wtot[32], woff[32];
    int f = 0;
    float sc = 0.0f;
    if (tid < TOPK) {
        sc = g_top_score[b * TOPK + tid];
        f = (int)((kbuf[cur][tid >> 6] >> (tid & 63)) & 1ull) & (sc > CONF ? 1 : 0);
    }
    unsigned bal = __ballot_sync(0xFFFFFFFFu, f);
    if (lane == 0) wtot[wid] = __popc(bal);
    __syncthreads();
    if (tid == 0) {
        int acc = 0;
        for (int i = 0; i < 32; i++) { woff[i] = acc; acc += wtot[i]; }
    }
    __syncthreads();
    int pos = woff[wid] + __popc(bal & ((1u << lane) - 1u));

    if (f && pos < MAXDET) {
        int o = b * TOPK + tid;
        ((float4*)ob)[pos] = ((const float4*)g_top_box)[o];
        os[pos] = sc;
        ol[pos] = (float)c_coco[g_top_label[o]];
    }
}

// ---------------- launch ----------------------------------------------------
extern "C" void kernel_launch(void* const* d_in, const int* in_sizes, int n_in,
                              void* d_out, int out_size) {
    (void)in_sizes; (void)n_in; (void)out_size;
    const float4* preds4 = (const float4*)d_in[0];
    float* out = (float*)d_out;

    cudaFuncSetAttribute(select_kernel,
                         cudaFuncAttributeMaxDynamicSharedMemorySize, SEL_SMEM);

    dim3 dgrid((NQUAD + 255) / 256, NB);
    decode_kernel<<<dgrid, 256>>>(preds4);
    select_kernel<<<NB, 1024, SEL_SMEM>>>();
    supbuild_kernel<<<dim3(NSLICE, NB), 1024>>>();
    resolve_kernel<<<NB, 1024>>>(out);
}

// round 6
// speedup vs baseline: 1.1200x; 1.1200x over previous
#include <cuda_runtime.h>
#include <cstdint>

#define NB      32
#define NCH     84
#define NCLS    80
#define NANCH   8400
#define NQUAD   2100          // NANCH / 4
#define TOPK    1000
#define MAXDET  300
#define GCAP    128           // per-label member list capacity
#define CONF    0.25f
#define IOU_THR 0.7f
#define MAX_WH  7680.0f
#define IMG_SZ  640.0f

// ---------------- scratch (device globals; no allocation allowed) ----------
__device__ unsigned long long g_key  [NB * NANCH];   // (fmap(score)<<32)|~idx
__device__ int                g_label[NB * NANCH];
__device__ float              g_box  [NB * NANCH * 4];
__device__ float              g_top_score[NB * TOPK];
__device__ int                g_top_label[NB * TOPK];
__device__ float              g_top_box  [NB * TOPK * 4];

__constant__ int c_coco[80] = {
    1,2,3,4,5,6,7,8,9,10,11,13,14,15,16,17,18,19,20,21,22,23,24,25,27,28,
    31,32,33,34,35,36,37,38,39,40,41,42,43,44,46,47,48,49,50,51,52,53,54,55,
    56,57,58,59,60,61,62,63,64,65,67,70,72,73,74,75,76,77,78,79,80,81,82,84,
    85,86,87,88,89,90
};

__device__ __forceinline__ unsigned int fmap(float f) {
    unsigned int u = __float_as_uint(f);
    return (u & 0x80000000u) ? ~u : (u | 0x80000000u);
}
__device__ __forceinline__ float funmap(unsigned int u) {
    return (u & 0x80000000u) ? __uint_as_float(u ^ 0x80000000u)
                             : __uint_as_float(~u);
}

// ---------------- stage 1: decode (float4, 4 anchors/thread) ---------------
__global__ void __launch_bounds__(256) decode_kernel(const float4* __restrict__ p4) {
    int g = blockIdx.x * blockDim.x + threadIdx.x;
    int b = blockIdx.y;
    if (g >= NQUAD) return;
    const float4* base = p4 + (size_t)b * (NCH * NQUAD) + g;

    float4 vx = base[0];
    float4 vy = base[NQUAD];
    float4 vw = base[2 * NQUAD];
    float4 vh = base[3 * NQUAD];

    float4 best = base[4 * NQUAD];
    int4   bi   = make_int4(0, 0, 0, 0);
#pragma unroll 16
    for (int c = 1; c < NCLS; c++) {
        float4 v = base[(4 + c) * NQUAD];
        if (v.x > best.x) { best.x = v.x; bi.x = c; }
        if (v.y > best.y) { best.y = v.y; bi.y = c; }
        if (v.z > best.z) { best.z = v.z; bi.z = c; }
        if (v.w > best.w) { best.w = v.w; bi.w = c; }
    }

    int o = b * NANCH + 4 * g;

    float s0 = (best.x > CONF) ? best.x : -1.0f;
    float s1 = (best.y > CONF) ? best.y : -1.0f;
    float s2 = (best.z > CONF) ? best.z : -1.0f;
    float s3 = (best.w > CONF) ? best.w : -1.0f;

    unsigned long long k0 = ((unsigned long long)fmap(s0) << 32) | (unsigned int)(~(4*g+0));
    unsigned long long k1 = ((unsigned long long)fmap(s1) << 32) | (unsigned int)(~(4*g+1));
    unsigned long long k2 = ((unsigned long long)fmap(s2) << 32) | (unsigned int)(~(4*g+2));
    unsigned long long k3 = ((unsigned long long)fmap(s3) << 32) | (unsigned int)(~(4*g+3));
    ((ulonglong2*)g_key)[o/2]     = make_ulonglong2(k0, k1);
    ((ulonglong2*)g_key)[o/2 + 1] = make_ulonglong2(k2, k3);

    ((int4*)g_label)[b * NQUAD + g] = bi;

    float4* boxo = (float4*)g_box + o;
    {
        float x = vx.x * IMG_SZ, y = vy.x * IMG_SZ, hw = vw.x * IMG_SZ * 0.5f, hh = vh.x * IMG_SZ * 0.5f;
        boxo[0] = make_float4(x - hw, y - hh, x + hw, y + hh);
    }
    {
        float x = vx.y * IMG_SZ, y = vy.y * IMG_SZ, hw = vw.y * IMG_SZ * 0.5f, hh = vh.y * IMG_SZ * 0.5f;
        boxo[1] = make_float4(x - hw, y - hh, x + hw, y + hh);
    }
    {
        float x = vx.z * IMG_SZ, y = vy.z * IMG_SZ, hw = vw.z * IMG_SZ * 0.5f, hh = vh.z * IMG_SZ * 0.5f;
        boxo[2] = make_float4(x - hw, y - hh, x + hw, y + hh);
    }
    {
        float x = vx.w * IMG_SZ, y = vy.w * IMG_SZ, hw = vw.w * IMG_SZ * 0.5f, hh = vh.w * IMG_SZ * 0.5f;
        boxo[3] = make_float4(x - hw, y - hh, x + hw, y + hh);
    }
}

// ---------------- stage 2: exact top-1000 via radix select + 1K sort -------
#define SEL_SMEM ((8448 + 1024) * 8)

__global__ void __launch_bounds__(1024) select_kernel() {
    extern __shared__ unsigned long long sm[];
    unsigned long long* key  = sm;          // 8400 (8448 pad)
    unsigned long long* cand = sm + 8448;   // 1024
    __shared__ int hist[256];
    __shared__ unsigned long long s_prefix;
    __shared__ int s_k, s_cnt;

    int b = blockIdx.x, tid = threadIdx.x;
    int lane = tid & 31;

    for (int i = tid; i < NANCH; i += 1024)
        key[i] = g_key[b * NANCH + i];
    if (tid == 0) { s_prefix = 0ull; s_k = TOPK; s_cnt = 0; }
    __syncthreads();

    const int shifts[6] = {56, 48, 40, 32, 8, 0};
#pragma unroll 1
    for (int pass = 0; pass < 6; ++pass) {
        if (tid < 256) hist[tid] = 0;
        __syncthreads();
        unsigned long long pfx = s_prefix;
        int shift = shifts[pass];
#pragma unroll 1
        for (int ii = 0; ii < 9; ++ii) {
            int i = tid + ii * 1024;
            unsigned long long v = (i < NANCH) ? key[i] : 0ull;
            bool act = (i < NANCH) &&
                       ((pass == 0) || ((v >> (shift + 8)) == pfx));
            int bin = act ? (int)((v >> shift) & 255ull) : (300 + lane);
            unsigned grp = __match_any_sync(0xFFFFFFFFu, bin);
            if (act && lane == (__ffs(grp) - 1))
                atomicAdd(&hist[bin], __popc(grp));
        }
        __syncthreads();
        if (tid == 0) {
            int k = s_k, d = 255;
            for (;; --d) { int h = hist[d]; if (h >= k) break; k -= h; }
            unsigned long long np = (pfx << 8) | (unsigned long long)d;
            if (pass == 3) np = (np << 16) | 0xFFFFull;   // ~idx high bits known
            s_prefix = np;
            s_k = k;
        }
        __syncthreads();
    }

    unsigned long long thr = s_prefix;    // exact 1000th-largest key
#pragma unroll 1
    for (int ii = 0; ii < 9; ++ii) {      // warp-aggregated compaction
        int i = tid + ii * 1024;
        unsigned long long v = (i < NANCH) ? key[i] : 0ull;
        bool win = (i < NANCH) && (v >= thr);
        unsigned bal = __ballot_sync(0xFFFFFFFFu, win);
        int base = 0;
        if (bal) {
            if (lane == 0) base = atomicAdd(&s_cnt, __popc(bal));
            base = __shfl_sync(0xFFFFFFFFu, base, 0);
            if (win) cand[base + __popc(bal & ((1u << lane) - 1u))] = v;
        }
    }
    __syncthreads();
    if (tid < 1024 - TOPK) cand[TOPK + tid] = 0ull;
    __syncthreads();

    for (int kk = 2; kk <= 1024; kk <<= 1) {
        for (int j = kk >> 1; j > 0; j >>= 1) {
            if (tid < 512) {
                int i = ((tid & ~(j - 1)) << 1) | (tid & (j - 1));
                int l = i | j;
                unsigned long long a = cand[i], c = cand[l];
                bool desc = ((i & kk) == 0);
                if (desc ? (a < c) : (a > c)) { cand[i] = c; cand[l] = a; }
            }
            __syncthreads();
        }
    }

    if (tid < TOPK) {
        unsigned long long kv = cand[tid];
        unsigned int idx = ~(unsigned int)(kv & 0xFFFFFFFFull);
        int src = b * NANCH + (int)idx;
        int o   = b * TOPK + tid;
        g_top_score[o] = funmap((unsigned int)(kv >> 32));  // exact round-trip
        g_top_label[o] = g_label[src];
        ((float4*)g_top_box)[o] = ((const float4*)g_box)[src];
    }
}

// ---------------- stage 3: per-label greedy NMS + compact + emit ------------
// Cross-label pairs can never suppress: offset boxes live in
// [label*7680 - 320, label*7680 + 960], so different labels have empty
// intersection -> inter = 0 -> iou = 0 < 0.7, exactly (denom > 0). Greedy NMS
// therefore decomposes into independent per-label greedy problems processed
// in global rank order. IoU uses the verified division-free interval test
// with exact-division fallback; operand order matches the reference
// (area_earlier + area_later - inter + 1e-7).
__global__ void __launch_bounds__(1024) nms_emit_kernel(float* __restrict__ out) {
    __shared__ float sx1[TOPK], sy1[TOPK], sx2[TOPK], sy2[TOPK], sar[TOPK];
    __shared__ unsigned short list[NCLS][GCAP];   // member ranks per label
    __shared__ unsigned char  slab[1024];
    __shared__ unsigned int   keepw[32];
    __shared__ int wtot[32], woff[32];

    int b = blockIdx.x, tid = threadIdx.x;
    int wid = tid >> 5, lane = tid & 31;

    float* ob = out + (size_t)b * MAXDET * 4;
    float* os = out + (size_t)NB * MAXDET * 4 + (size_t)b * MAXDET;
    float* ol = out + (size_t)NB * MAXDET * 5 + (size_t)b * MAXDET;

    for (int t = tid; t < MAXDET; t += 1024) {
        ((float4*)ob)[t] = make_float4(0.f, 0.f, 0.f, 0.f);
        os[t] = 0.0f;
        ol[t] = 0.0f;
    }
    if (tid < 32) keepw[tid] = 0u;
    if (tid >= TOPK) slab[tid] = 0xFF;

    for (int t = tid; t < TOPK; t += 1024) {
        int o = b * TOPK + t;
        int lb = g_top_label[o];
        slab[t] = (unsigned char)lb;
        float off = (float)lb * MAX_WH;
        float4 bx = ((const float4*)g_top_box)[o];
        float a0 = bx.x + off, a1 = bx.y + off, a2 = bx.z + off, a3 = bx.w + off;
        sx1[t] = a0; sy1[t] = a1; sx2[t] = a2; sy2[t] = a3;
        sar[t] = (a2 - a0) * (a3 - a1);
    }
    __syncthreads();

    const float HI = 0.7000007f;
    const float LO = 0.6999993f;

    // each warp owns labels wid, wid+32, wid+64
    for (int l = wid; l < NCLS; l += 32) {
        // collect members of label l in rank order (ballot scan)
        int cnt = 0;
#pragma unroll 1
        for (int c = 0; c < 32; ++c) {
            int rank = c * 32 + lane;
            bool m = (slab[rank] == (unsigned char)l);
            unsigned bal = __ballot_sync(0xFFFFFFFFu, m);
            if (m) {
                int pos = cnt + __popc(bal & ((1u << lane) - 1u));
                if (pos < GCAP) list[l][pos] = (unsigned short)rank;
            }
            cnt += __popc(bal);
        }
        int g = min(cnt, GCAP);

        // greedy within the group, serial over members, lanes over kept
        unsigned long long kept0 = 0ull, kept1 = 0ull;
#pragma unroll 1
        for (int m = 0; m < g; ++m) {
            int rm = list[l][m];
            float cx1 = sx1[rm], cy1 = sy1[rm], cx2 = sx2[rm], cy2 = sy2[rm];
            float ca  = sar[rm];
            bool sup = false;
#pragma unroll 1
            for (int base = 0; base < m; base += 32) {
                int mi = base + lane;
                bool valid = (mi < m) &&
                    (((mi < 64) ? (kept0 >> mi) : (kept1 >> (mi - 64))) & 1ull);
                bool s = false;
                if (valid) {
                    int ri = list[l][mi];
                    float lx = fmaxf(sx1[ri], cx1);
                    float ly = fmaxf(sy1[ri], cy1);
                    float rx = fminf(sx2[ri], cx2);
                    float ry = fminf(sy2[ri], cy2);
                    float wd = fmaxf(rx - lx, 0.0f);
                    float ht = fmaxf(ry - ly, 0.0f);
                    float inter = wd * ht;
                    float denom = sar[ri] + ca - inter + 1e-7f;
                    if (inter > HI * denom)      s = true;
                    else if (inter >= LO * denom) s = (inter / denom) > IOU_THR;
                }
                if (__ballot_sync(0xFFFFFFFFu, s)) { sup = true; break; }
            }
            if (!sup) {
                if (m < 64) kept0 |= 1ull << m; else kept1 |= 1ull << (m - 64);
                if (lane == 0) atomicOr(&keepw[rm >> 5], 1u << (rm & 31));
            }
        }
    }
    __syncthreads();

    // conf gate + block scan + scatter (kept are already score-descending)
    int f = 0;
    float sc = 0.0f;
    if (tid < TOPK) {
        sc = g_top_score[b * TOPK + tid];
        f = (int)((keepw[tid >> 5] >> (tid & 31)) & 1u) & (sc > CONF ? 1 : 0);
    }
    unsigned bal = __ballot_sync(0xFFFFFFFFu, f);
    if (lane == 0) wtot[wid] = __popc(bal);
    __syncthreads();
    if (tid == 0) {
        int acc = 0;
        for (int i = 0; i < 32; i++) { woff[i] = acc; acc += wtot[i]; }
    }
    __syncthreads();
    int pos = woff[wid] + __popc(bal & ((1u << lane) - 1u));

    if (f && pos < MAXDET) {
        int o = b * TOPK + tid;
        ((float4*)ob)[pos] = ((const float4*)g_top_box)[o];
        os[pos] = sc;
        ol[pos] = (float)c_coco[g_top_label[o]];
    }
}

// ---------------- launch ----------------------------------------------------
extern "C" void kernel_launch(void* const* d_in, const int* in_sizes, int n_in,
                              void* d_out, int out_size) {
    (void)in_sizes; (void)n_in; (void)out_size;
    const float4* preds4 = (const float4*)d_in[0];
    float* out = (float*)d_out;

    cudaFuncSetAttribute(select_kernel,
                         cudaFuncAttributeMaxDynamicSharedMemorySize, SEL_SMEM);

    dim3 dgrid((NQUAD + 255) / 256, NB);
    decode_kernel<<<dgrid, 256>>>(preds4);
    select_kernel<<<NB, 1024, SEL_SMEM>>>();
    nms_emit_kernel<<<NB, 1024>>>(out);
}

// round 7
// speedup vs baseline: 1.7997x; 1.6069x over previous
#include <cuda_runtime.h>
#include <cstdint>

#define NB      32
#define NCH     84
#define NCLS    80
#define NANCH   8400
#define NQUAD   2100          // NANCH / 4
#define TOPK    1000
#define MAXDET  300
#define GCAP    128           // per-label member list capacity
#define CONF    0.25f
#define IOU_THR 0.7f
#define MAX_WH  7680.0f
#define IMG_SZ  640.0f

// ---------------- scratch (device globals; no allocation allowed) ----------
__device__ unsigned long long g_key  [NB * NANCH];   // (fmap(score)<<32)|~idx
__device__ int                g_label[NB * NANCH];
__device__ float              g_box  [NB * NANCH * 4];
__device__ float              g_top_score[NB * TOPK];
__device__ int                g_top_label[NB * TOPK];
__device__ float              g_top_box  [NB * TOPK * 4];

__constant__ int c_coco[80] = {
    1,2,3,4,5,6,7,8,9,10,11,13,14,15,16,17,18,19,20,21,22,23,24,25,27,28,
    31,32,33,34,35,36,37,38,39,40,41,42,43,44,46,47,48,49,50,51,52,53,54,55,
    56,57,58,59,60,61,62,63,64,65,67,70,72,73,74,75,76,77,78,79,80,81,82,84,
    85,86,87,88,89,90
};

__device__ __forceinline__ unsigned int fmap(float f) {
    unsigned int u = __float_as_uint(f);
    return (u & 0x80000000u) ? ~u : (u | 0x80000000u);
}
__device__ __forceinline__ float funmap(unsigned int u) {
    return (u & 0x80000000u) ? __uint_as_float(u ^ 0x80000000u)
                             : __uint_as_float(~u);
}

// ---------------- stage 1: decode (float4, 4 anchors/thread) ---------------
__global__ void __launch_bounds__(256) decode_kernel(const float4* __restrict__ p4) {
    int g = blockIdx.x * blockDim.x + threadIdx.x;
    int b = blockIdx.y;
    if (g >= NQUAD) return;
    const float4* base = p4 + (size_t)b * (NCH * NQUAD) + g;

    float4 vx = base[0];
    float4 vy = base[NQUAD];
    float4 vw = base[2 * NQUAD];
    float4 vh = base[3 * NQUAD];

    float4 best = base[4 * NQUAD];
    int4   bi   = make_int4(0, 0, 0, 0);
#pragma unroll 16
    for (int c = 1; c < NCLS; c++) {
        float4 v = base[(4 + c) * NQUAD];
        if (v.x > best.x) { best.x = v.x; bi.x = c; }
        if (v.y > best.y) { best.y = v.y; bi.y = c; }
        if (v.z > best.z) { best.z = v.z; bi.z = c; }
        if (v.w > best.w) { best.w = v.w; bi.w = c; }
    }

    int o = b * NANCH + 4 * g;

    float s0 = (best.x > CONF) ? best.x : -1.0f;
    float s1 = (best.y > CONF) ? best.y : -1.0f;
    float s2 = (best.z > CONF) ? best.z : -1.0f;
    float s3 = (best.w > CONF) ? best.w : -1.0f;

    unsigned long long k0 = ((unsigned long long)fmap(s0) << 32) | (unsigned int)(~(4*g+0));
    unsigned long long k1 = ((unsigned long long)fmap(s1) << 32) | (unsigned int)(~(4*g+1));
    unsigned long long k2 = ((unsigned long long)fmap(s2) << 32) | (unsigned int)(~(4*g+2));
    unsigned long long k3 = ((unsigned long long)fmap(s3) << 32) | (unsigned int)(~(4*g+3));
    ((ulonglong2*)g_key)[o/2]     = make_ulonglong2(k0, k1);
    ((ulonglong2*)g_key)[o/2 + 1] = make_ulonglong2(k2, k3);

    ((int4*)g_label)[b * NQUAD + g] = bi;

    float4* boxo = (float4*)g_box + o;
    {
        float x = vx.x * IMG_SZ, y = vy.x * IMG_SZ, hw = vw.x * IMG_SZ * 0.5f, hh = vh.x * IMG_SZ * 0.5f;
        boxo[0] = make_float4(x - hw, y - hh, x + hw, y + hh);
    }
    {
        float x = vx.y * IMG_SZ, y = vy.y * IMG_SZ, hw = vw.y * IMG_SZ * 0.5f, hh = vh.y * IMG_SZ * 0.5f;
        boxo[1] = make_float4(x - hw, y - hh, x + hw, y + hh);
    }
    {
        float x = vx.z * IMG_SZ, y = vy.z * IMG_SZ, hw = vw.z * IMG_SZ * 0.5f, hh = vh.z * IMG_SZ * 0.5f;
        boxo[2] = make_float4(x - hw, y - hh, x + hw, y + hh);
    }
    {
        float x = vx.w * IMG_SZ, y = vy.w * IMG_SZ, hw = vw.w * IMG_SZ * 0.5f, hh = vh.w * IMG_SZ * 0.5f;
        boxo[3] = make_float4(x - hw, y - hh, x + hw, y + hh);
    }
}

// ---------------- stage 2: exact top-1000 via radix select + 1K sort -------
// 6 byte-passes over the 64-bit key (bits 31:16 spliced: ~idx high bits are
// always 0xFFFF). After the two top passes the active set is compacted to
// the keys matching the 16-bit prefix; passes 2-5 scan only those.
// Threshold digit found by warp-0 parallel suffix scan. Final 1024 sort is a
// register bitonic (shfl for j<32, smem for j>=32).
#define SEL_SMEM ((8448 + 8448 + 1024) * 8)

__global__ void __launch_bounds__(1024) select_kernel() {
    extern __shared__ unsigned long long sm[];
    unsigned long long* key  = sm;            // 8400 (8448 pad)
    unsigned long long* actl = sm + 8448;     // compacted active keys
    unsigned long long* cand = sm + 16896;    // 1024
    __shared__ int hist[8][256];
    __shared__ int hfin[256];
    __shared__ unsigned long long s_prefix;
    __shared__ int s_k, s_cnt, s_actn;

    int b = blockIdx.x, tid = threadIdx.x;
    int wid = tid >> 5, lane = tid & 31;
    const unsigned FULL = 0xFFFFFFFFu;
    unsigned lmask = (1u << lane) - 1u;

    for (int i = tid; i < NANCH; i += 1024)
        key[i] = g_key[b * NANCH + i];
    if (tid == 0) { s_prefix = 0ull; s_k = TOPK; s_cnt = 0; s_actn = 0; }
    __syncthreads();

    const int shifts[6] = {56, 48, 40, 32, 8, 0};
#pragma unroll 1
    for (int pass = 0; pass < 6; ++pass) {
        // zero replicated histograms
        for (int i = tid; i < 8 * 256; i += 1024) ((int*)hist)[i] = 0;
        __syncthreads();

        unsigned long long pfx = s_prefix;
        int shift = shifts[pass];
        const unsigned long long* arr = (pass < 2) ? key : actl;
        int n = (pass < 2) ? NANCH : s_actn;
        int iters = (n + 1023) >> 10;
        int sub = wid & 7;

#pragma unroll 1
        for (int ii = 0; ii < iters; ++ii) {
            int i = tid + (ii << 10);
            unsigned long long v = (i < n) ? arr[i] : 0ull;
            bool a = (i < n) && ((pass == 0) || ((v >> (shift + 8)) == pfx));
            int bin = (int)((v >> shift) & 255ull);
            unsigned am = __ballot_sync(FULL, a);
            if (am == FULL) {
                int b0 = __shfl_sync(FULL, bin, 0);
                if (__all_sync(FULL, bin == b0)) {   // uniform fast path
                    if (lane == 0) atomicAdd(&hist[sub][b0], 32);
                    continue;
                }
            }
            if (a) atomicAdd(&hist[sub][bin], 1);
        }
        __syncthreads();

        if (tid < 256) {
            int s = 0;
#pragma unroll
            for (int h = 0; h < 8; ++h) s += hist[h][tid];
            hfin[tid] = s;
        }
        __syncthreads();

        // warp 0: parallel suffix scan to find threshold digit + new k
        if (tid < 32) {
            int chunk[8];
            int tot = 0;
#pragma unroll
            for (int e = 0; e < 8; ++e) { chunk[e] = hfin[tid * 8 + e]; tot += chunk[e]; }
            int suf = tot;
#pragma unroll
            for (int o = 1; o < 32; o <<= 1) {
                int v = __shfl_down_sync(FULL, suf, o);
                if (tid + o < 32) suf += v;
            }
            int S = suf - tot;                 // strict suffix over lanes > tid
            int k = s_k;
#pragma unroll
            for (int e = 7; e >= 0; --e) {
                int h = chunk[e];
                if (k > S && k <= S + h) {     // exactly one (lane, e) matches
                    unsigned long long np = (s_prefix << 8) | (unsigned long long)(tid * 8 + e);
                    if (shift == 32) np = (np << 16) | 0xFFFFull;  // ~idx high bits
                    s_prefix = np;
                    s_k = k - S;
                }
                S += h;
            }
        }
        __syncthreads();

        // after pass 1: compact the active set (keys matching 16-bit prefix)
        if (pass == 1) {
            unsigned long long p16 = s_prefix;
#pragma unroll 1
            for (int ii = 0; ii < 9; ++ii) {
                int i = tid + (ii << 10);
                unsigned long long v = (i < NANCH) ? key[i] : 0ull;
                bool m = (i < NANCH) && ((v >> 48) == p16);
                unsigned bal = __ballot_sync(FULL, m);
                if (bal) {
                    int base = 0;
                    if (lane == 0) base = atomicAdd(&s_actn, __popc(bal));
                    base = __shfl_sync(FULL, base, 0);
                    if (m) actl[base + __popc(bal & lmask)] = v;
                }
            }
            __syncthreads();
        }
    }

    // gather winners: exactly TOPK keys >= thr
    unsigned long long thr = s_prefix;
#pragma unroll 1
    for (int ii = 0; ii < 9; ++ii) {
        int i = tid + (ii << 10);
        unsigned long long v = (i < NANCH) ? key[i] : 0ull;
        bool win = (i < NANCH) && (v >= thr);
        unsigned bal = __ballot_sync(FULL, win);
        if (bal) {
            int base = 0;
            if (lane == 0) base = atomicAdd(&s_cnt, __popc(bal));
            base = __shfl_sync(FULL, base, 0);
            if (win) cand[base + __popc(bal & lmask)] = v;
        }
    }
    __syncthreads();

    // register bitonic sort, descending; thread tid owns element tid
    unsigned long long r = (tid < TOPK) ? cand[tid] : 0ull;
#pragma unroll 1
    for (int kk = 2; kk <= 1024; kk <<= 1) {
#pragma unroll 1
        for (int j = kk >> 1; j > 0; j >>= 1) {
            unsigned long long o;
            if (j >= 32) {
                __syncthreads();
                cand[tid] = r;
                __syncthreads();
                o = cand[tid ^ j];
            } else {
                o = __shfl_xor_sync(FULL, r, j);
            }
            bool up    = ((tid & kk) == 0);
            bool lower = ((tid & j) == 0);
            unsigned long long mx = (r > o) ? r : o;
            unsigned long long mn = (r > o) ? o : r;
            r = (up == lower) ? mx : mn;
        }
    }

    if (tid < TOPK) {
        unsigned int idx = ~(unsigned int)(r & 0xFFFFFFFFull);
        int src = b * NANCH + (int)idx;
        int o   = b * TOPK + tid;
        g_top_score[o] = funmap((unsigned int)(r >> 32));   // exact round-trip
        g_top_label[o] = g_label[src];
        ((float4*)g_top_box)[o] = ((const float4*)g_box)[src];
    }
}

// ---------------- stage 3: per-label greedy NMS + compact + emit ------------
// Cross-label pairs can never suppress (offset boxes of different labels are
// disjoint -> iou = 0 exactly), so greedy NMS decomposes per label.
__global__ void __launch_bounds__(1024) nms_emit_kernel(float* __restrict__ out) {
    __shared__ float sx1[TOPK], sy1[TOPK], sx2[TOPK], sy2[TOPK], sar[TOPK];
    __shared__ unsigned short list[NCLS][GCAP];
    __shared__ unsigned char  slab[1024];
    __shared__ unsigned int   keepw[32];
    __shared__ int wtot[32], woff[32];

    int b = blockIdx.x, tid = threadIdx.x;
    int wid = tid >> 5, lane = tid & 31;

    float* ob = out + (size_t)b * MAXDET * 4;
    float* os = out + (size_t)NB * MAXDET * 4 + (size_t)b * MAXDET;
    float* ol = out + (size_t)NB * MAXDET * 5 + (size_t)b * MAXDET;

    for (int t = tid; t < MAXDET; t += 1024) {
        ((float4*)ob)[t] = make_float4(0.f, 0.f, 0.f, 0.f);
        os[t] = 0.0f;
        ol[t] = 0.0f;
    }
    if (tid < 32) keepw[tid] = 0u;
    if (tid >= TOPK) slab[tid] = 0xFF;

    for (int t = tid; t < TOPK; t += 1024) {
        int o = b * TOPK + t;
        int lb = g_top_label[o];
        slab[t] = (unsigned char)lb;
        float off = (float)lb * MAX_WH;
        float4 bx = ((const float4*)g_top_box)[o];
        float a0 = bx.x + off, a1 = bx.y + off, a2 = bx.z + off, a3 = bx.w + off;
        sx1[t] = a0; sy1[t] = a1; sx2[t] = a2; sy2[t] = a3;
        sar[t] = (a2 - a0) * (a3 - a1);
    }
    __syncthreads();

    const float HI = 0.7000007f;
    const float LO = 0.6999993f;

    for (int l = wid; l < NCLS; l += 32) {
        int cnt = 0;
#pragma unroll 1
        for (int c = 0; c < 32; ++c) {
            int rank = c * 32 + lane;
            bool m = (slab[rank] == (unsigned char)l);
            unsigned bal = __ballot_sync(0xFFFFFFFFu, m);
            if (m) {
                int pos = cnt + __popc(bal & ((1u << lane) - 1u));
                if (pos < GCAP) list[l][pos] = (unsigned short)rank;
            }
            cnt += __popc(bal);
        }
        int g = min(cnt, GCAP);

        unsigned long long kept0 = 0ull, kept1 = 0ull;
#pragma unroll 1
        for (int m = 0; m < g; ++m) {
            int rm = list[l][m];
            float cx1 = sx1[rm], cy1 = sy1[rm], cx2 = sx2[rm], cy2 = sy2[rm];
            float ca  = sar[rm];
            bool sup = false;
#pragma unroll 1
            for (int base = 0; base < m; base += 32) {
                int mi = base + lane;
                bool valid = (mi < m) &&
                    (((mi < 64) ? (kept0 >> mi) : (kept1 >> (mi - 64))) & 1ull);
                bool s = false;
                if (valid) {
                    int ri = list[l][mi];
                    float lx = fmaxf(sx1[ri], cx1);
                    float ly = fmaxf(sy1[ri], cy1);
                    float rx = fminf(sx2[ri], cx2);
                    float ry = fminf(sy2[ri], cy2);
                    float wd = fmaxf(rx - lx, 0.0f);
                    float ht = fmaxf(ry - ly, 0.0f);
                    float inter = wd * ht;
                    float denom = sar[ri] + ca - inter + 1e-7f;
                    if (inter > HI * denom)      s = true;
                    else if (inter >= LO * denom) s = (inter / denom) > IOU_THR;
                }
                if (__ballot_sync(0xFFFFFFFFu, s)) { sup = true; break; }
            }
            if (!sup) {
                if (m < 64) kept0 |= 1ull << m; else kept1 |= 1ull << (m - 64);
                if (lane == 0) atomicOr(&keepw[rm >> 5], 1u << (rm & 31));
            }
        }
    }
    __syncthreads();

    int f = 0;
    float sc = 0.0f;
    if (tid < TOPK) {
        sc = g_top_score[b * TOPK + tid];
        f = (int)((keepw[tid >> 5] >> (tid & 31)) & 1u) & (sc > CONF ? 1 : 0);
    }
    unsigned bal = __ballot_sync(0xFFFFFFFFu, f);
    if (lane == 0) wtot[wid] = __popc(bal);
    __syncthreads();
    if (tid == 0) {
        int acc = 0;
        for (int i = 0; i < 32; i++) { woff[i] = acc; acc += wtot[i]; }
    }
    __syncthreads();
    int pos = woff[wid] + __popc(bal & ((1u << lane) - 1u));

    if (f && pos < MAXDET) {
        int o = b * TOPK + tid;
        ((float4*)ob)[pos] = ((const float4*)g_top_box)[o];
        os[pos] = sc;
        ol[pos] = (float)c_coco[g_top_label[o]];
    }
}

// ---------------- launch ----------------------------------------------------
extern "C" void kernel_launch(void* const* d_in, const int* in_sizes, int n_in,
                              void* d_out, int out_size) {
    (void)in_sizes; (void)n_in; (void)out_size;
    const float4* preds4 = (const float4*)d_in[0];
    float* out = (float*)d_out;

    cudaFuncSetAttribute(select_kernel,
                         cudaFuncAttributeMaxDynamicSharedMemorySize, SEL_SMEM);

    dim3 dgrid((NQUAD + 255) / 256, NB);
    decode_kernel<<<dgrid, 256>>>(preds4);
    select_kernel<<<NB, 1024, SEL_SMEM>>>();
    nms_emit_kernel<<<NB, 1024>>>(out);
}

// round 8
// speedup vs baseline: 1.8436x; 1.0244x over previous
#include <cuda_runtime.h>
#include <cstdint>

#define NB      32
#define NCH     84
#define NCLS    80
#define NANCH   8400
#define NQUAD   2100          // NANCH / 4
#define TOPK    1000
#define MAXDET  300
#define GCAP    128           // per-label member list capacity
#define CONF    0.25f
#define IOU_THR 0.7f
#define MAX_WH  7680.0f
#define IMG_SZ  640.0f

// ---------------- scratch (device globals; no allocation allowed) ----------
__device__ unsigned long long g_key  [NB * NANCH];   // (fmap(score)<<32)|~idx
__device__ int                g_label[NB * NANCH];
__device__ float              g_box  [NB * NANCH * 4];

__constant__ int c_coco[80] = {
    1,2,3,4,5,6,7,8,9,10,11,13,14,15,16,17,18,19,20,21,22,23,24,25,27,28,
    31,32,33,34,35,36,37,38,39,40,41,42,43,44,46,47,48,49,50,51,52,53,54,55,
    56,57,58,59,60,61,62,63,64,65,67,70,72,73,74,75,76,77,78,79,80,81,82,84,
    85,86,87,88,89,90
};

__device__ __forceinline__ unsigned int fmap(float f) {
    unsigned int u = __float_as_uint(f);
    return (u & 0x80000000u) ? ~u : (u | 0x80000000u);
}
__device__ __forceinline__ float funmap(unsigned int u) {
    return (u & 0x80000000u) ? __uint_as_float(u ^ 0x80000000u)
                             : __uint_as_float(~u);
}

// ---------------- stage 1: decode (channel-split pairs, float4 quads) ------
// Two threads per quad: even lane handles classes 0..39 + box channels, odd
// lane classes 40..79. Combine via shfl with exact jnp.argmax semantics:
// odd's max wins only on strict > (equal -> even, which holds lower class
// indices). Doubles resident warps (2100 -> 4200) for latency cover.
__global__ void __launch_bounds__(256) decode_kernel(const float4* __restrict__ p4) {
    int t = blockIdx.x * blockDim.x + threadIdx.x;
    int pair = t >> 1;
    int half = t & 1;
    int b = blockIdx.y;
    bool valid = (pair < NQUAD);
    int g = valid ? pair : (NQUAD - 1);          // clamp; invalid lanes masked at write
    const float4* base = p4 + (size_t)b * (NCH * NQUAD) + g;
    const float4* cb   = base + (size_t)(4 + (half ? 40 : 0)) * NQUAD;

    // box channels (odd lanes duplicate even's addresses -> coalesced, no extra DRAM)
    float4 vx = base[0];
    float4 vy = base[NQUAD];
    float4 vw = base[2 * NQUAD];
    float4 vh = base[3 * NQUAD];

    float4 best = cb[0];
    int4   bi   = make_int4(0, 0, 0, 0);
#pragma unroll
    for (int c = 1; c < 40; c++) {
        float4 v = cb[(size_t)c * NQUAD];
        if (v.x > best.x) { best.x = v.x; bi.x = c; }
        if (v.y > best.y) { best.y = v.y; bi.y = c; }
        if (v.z > best.z) { best.z = v.z; bi.z = c; }
        if (v.w > best.w) { best.w = v.w; bi.w = c; }
    }

    const unsigned FULL = 0xFFFFFFFFu;
    float obx = __shfl_down_sync(FULL, best.x, 1);
    float oby = __shfl_down_sync(FULL, best.y, 1);
    float obz = __shfl_down_sync(FULL, best.z, 1);
    float obw = __shfl_down_sync(FULL, best.w, 1);
    int   oix = __shfl_down_sync(FULL, bi.x, 1);
    int   oiy = __shfl_down_sync(FULL, bi.y, 1);
    int   oiz = __shfl_down_sync(FULL, bi.z, 1);
    int   oiw = __shfl_down_sync(FULL, bi.w, 1);

    if (half == 0 && valid) {
        if (obx > best.x) { best.x = obx; bi.x = oix + 40; }
        if (oby > best.y) { best.y = oby; bi.y = oiy + 40; }
        if (obz > best.z) { best.z = obz; bi.z = oiz + 40; }
        if (obw > best.w) { best.w = obw; bi.w = oiw + 40; }

        int o = b * NANCH + 4 * g;

        float s0 = (best.x > CONF) ? best.x : -1.0f;
        float s1 = (best.y > CONF) ? best.y : -1.0f;
        float s2 = (best.z > CONF) ? best.z : -1.0f;
        float s3 = (best.w > CONF) ? best.w : -1.0f;

        unsigned long long k0 = ((unsigned long long)fmap(s0) << 32) | (unsigned int)(~(4*g+0));
        unsigned long long k1 = ((unsigned long long)fmap(s1) << 32) | (unsigned int)(~(4*g+1));
        unsigned long long k2 = ((unsigned long long)fmap(s2) << 32) | (unsigned int)(~(4*g+2));
        unsigned long long k3 = ((unsigned long long)fmap(s3) << 32) | (unsigned int)(~(4*g+3));
        ((ulonglong2*)g_key)[o/2]     = make_ulonglong2(k0, k1);
        ((ulonglong2*)g_key)[o/2 + 1] = make_ulonglong2(k2, k3);

        ((int4*)g_label)[b * NQUAD + g] = bi;

        float4* boxo = (float4*)g_box + o;
        {
            float x = vx.x * IMG_SZ, y = vy.x * IMG_SZ, hw = vw.x * IMG_SZ * 0.5f, hh = vh.x * IMG_SZ * 0.5f;
            boxo[0] = make_float4(x - hw, y - hh, x + hw, y + hh);
        }
        {
            float x = vx.y * IMG_SZ, y = vy.y * IMG_SZ, hw = vw.y * IMG_SZ * 0.5f, hh = vh.y * IMG_SZ * 0.5f;
            boxo[1] = make_float4(x - hw, y - hh, x + hw, y + hh);
        }
        {
            float x = vx.z * IMG_SZ, y = vy.z * IMG_SZ, hw = vw.z * IMG_SZ * 0.5f, hh = vh.z * IMG_SZ * 0.5f;
            boxo[2] = make_float4(x - hw, y - hh, x + hw, y + hh);
        }
        {
            float x = vx.w * IMG_SZ, y = vy.w * IMG_SZ, hw = vw.w * IMG_SZ * 0.5f, hh = vh.w * IMG_SZ * 0.5f;
            boxo[3] = make_float4(x - hw, y - hh, x + hw, y + hh);
        }
    }
}

// ---------------- stage 2: fused select + per-label NMS + emit --------------
// Phase A: exact top-1000 radix select (6 byte-passes, active-set compaction
// after pass 1, sure-winner gather fused into the compaction scan, final
// gather over the small active set only) + register bitonic sort.
// Phase B: per-label greedy NMS (cross-label suppression impossible with
// class-offset boxes) + compact + emit. NMS arrays alias the dead active-set
// buffer; no global round-trip of top candidates.
#define SEL_SMEM ((8448 + 8448 + 1024) * 8)

__global__ void __launch_bounds__(1024) fused_kernel(float* __restrict__ out) {
    extern __shared__ unsigned long long sm[];
    unsigned long long* key  = sm;            // 8400 (8448 pad)
    unsigned long long* actl = sm + 8448;     // active set; aliased by NMS arrays later
    unsigned long long* cand = sm + 16896;    // 1024

    // NMS aliases over actl (41.5KB of 67.5KB) — actl dead after phase A
    float*          nx1  = (float*)actl;
    float*          ny1  = nx1 + TOPK;
    float*          nx2  = ny1 + TOPK;
    float*          ny2  = nx2 + TOPK;
    float*          nar  = ny2 + TOPK;
    unsigned short* list = (unsigned short*)(nar + TOPK);   // [NCLS][GCAP]
    unsigned char*  slab = (unsigned char*)(list + NCLS * GCAP);

    __shared__ int hist[8][256];
    __shared__ int hfin[256];
    __shared__ unsigned long long s_prefix;
    __shared__ int s_k, s_cnt, s_actn;
    __shared__ unsigned int keepw[32];
    __shared__ int wtot[32], woff[32];

    int b = blockIdx.x, tid = threadIdx.x;
    int wid = tid >> 5, lane = tid & 31;
    const unsigned FULL = 0xFFFFFFFFu;
    unsigned lmask = (1u << lane) - 1u;

    float* ob = out + (size_t)b * MAXDET * 4;
    float* os = out + (size_t)NB * MAXDET * 4 + (size_t)b * MAXDET;
    float* ol = out + (size_t)NB * MAXDET * 5 + (size_t)b * MAXDET;

    for (int i = tid; i < NANCH; i += 1024)
        key[i] = g_key[b * NANCH + i];
    if (tid == 0) { s_prefix = 0ull; s_k = TOPK; s_cnt = 0; s_actn = 0; }
    __syncthreads();

    const int shifts[6] = {56, 48, 40, 32, 8, 0};
#pragma unroll 1
    for (int pass = 0; pass < 6; ++pass) {
        for (int i = tid; i < 8 * 256; i += 1024) ((int*)hist)[i] = 0;
        __syncthreads();

        unsigned long long pfx = s_prefix;
        int shift = shifts[pass];
        const unsigned long long* arr = (pass < 2) ? key : actl;
        int n = (pass < 2) ? NANCH : s_actn;
        int iters = (n + 1023) >> 10;
        int sub = wid & 7;

#pragma unroll 1
        for (int ii = 0; ii < iters; ++ii) {
            int i = tid + (ii << 10);
            unsigned long long v = (i < n) ? arr[i] : 0ull;
            bool a = (i < n) && ((pass == 0) || ((v >> (shift + 8)) == pfx));
            int bin = (int)((v >> shift) & 255ull);
            unsigned am = __ballot_sync(FULL, a);
            if (am == FULL) {
                int b0 = __shfl_sync(FULL, bin, 0);
                if (__all_sync(FULL, bin == b0)) {           // uniform fast path
                    if (lane == 0) atomicAdd(&hist[sub][b0], 32);
                    continue;
                }
            }
            if (a) atomicAdd(&hist[sub][bin], 1);
        }
        __syncthreads();

        if (tid < 256) {
            int s = 0;
#pragma unroll
            for (int h = 0; h < 8; ++h) s += hist[h][tid];
            hfin[tid] = s;
        }
        __syncthreads();

        // warp 0: parallel suffix scan -> threshold digit + new k
        if (tid < 32) {
            int chunk[8];
            int tot = 0;
#pragma unroll
            for (int e = 0; e < 8; ++e) { chunk[e] = hfin[tid * 8 + e]; tot += chunk[e]; }
            int suf = tot;
#pragma unroll
            for (int o = 1; o < 32; o <<= 1) {
                int v = __shfl_down_sync(FULL, suf, o);
                if (tid + o < 32) suf += v;
            }
            int S = suf - tot;
            int k = s_k;
#pragma unroll
            for (int e = 7; e >= 0; --e) {
                int h = chunk[e];
                if (k > S && k <= S + h) {
                    unsigned long long np = (s_prefix << 8) | (unsigned long long)(tid * 8 + e);
                    if (shift == 32) np = (np << 16) | 0xFFFFull;  // ~idx high bits known
                    s_prefix = np;
                    s_k = k - S;
                }
                S += h;
            }
        }
        __syncthreads();

        // after pass 1: compact active set AND gather sure winners in one scan
        if (pass == 1) {
            unsigned long long p16 = s_prefix;
#pragma unroll 1
            for (int ii = 0; ii < 9; ++ii) {
                int i = tid + (ii << 10);
                unsigned long long v = (i < NANCH) ? key[i] : 0ull;
                unsigned long long hi = v >> 48;
                bool m  = (i < NANCH) && (hi == p16);   // active (threshold bin)
                bool sw = (i < NANCH) && (hi > p16);    // sure winner
                unsigned balm = __ballot_sync(FULL, m);
                if (balm) {
                    int base = 0;
                    if (lane == 0) base = atomicAdd(&s_actn, __popc(balm));
                    base = __shfl_sync(FULL, base, 0);
                    if (m) actl[base + __popc(balm & lmask)] = v;
                }
                unsigned balw = __ballot_sync(FULL, sw);
                if (balw) {
                    int base = 0;
                    if (lane == 0) base = atomicAdd(&s_cnt, __popc(balw));
                    base = __shfl_sync(FULL, base, 0);
                    if (sw) cand[base + __popc(balw & lmask)] = v;
                }
            }
            __syncthreads();
        }
    }

    // remaining winners: keys >= thr within the active set (exactly TOPK - s_cnt)
    {
        unsigned long long thr = s_prefix;
        int n2 = s_actn;
        int iters = (n2 + 1023) >> 10;
#pragma unroll 1
        for (int ii = 0; ii < iters; ++ii) {
            int i = tid + (ii << 10);
            unsigned long long v = (i < n2) ? actl[i] : 0ull;
            bool win = (i < n2) && (v >= thr);
            unsigned bal = __ballot_sync(FULL, win);
            if (bal) {
                int base = 0;
                if (lane == 0) base = atomicAdd(&s_cnt, __popc(bal));
                base = __shfl_sync(FULL, base, 0);
                if (win) cand[base + __popc(bal & lmask)] = v;
            }
        }
    }
    __syncthreads();
    if (tid < 1024 - TOPK) cand[TOPK + tid] = 0ull;
    __syncthreads();

    // register bitonic sort, descending
    unsigned long long r = (tid < TOPK) ? cand[tid] : 0ull;
#pragma unroll 1
    for (int kk = 2; kk <= 1024; kk <<= 1) {
#pragma unroll 1
        for (int j = kk >> 1; j > 0; j >>= 1) {
            unsigned long long o;
            if (j >= 32) {
                __syncthreads();
                cand[tid] = r;
                __syncthreads();
                o = cand[tid ^ j];
            } else {
                o = __shfl_xor_sync(FULL, r, j);
            }
            bool up    = ((tid & kk) == 0);
            bool lower = ((tid & j) == 0);
            unsigned long long mx = (r > o) ? r : o;
            unsigned long long mn = (r > o) ? o : r;
            r = (up == lower) ? mx : mn;
        }
    }

    // ---------------- phase B: gather + per-label NMS + emit ----------------
    for (int t = tid; t < MAXDET; t += 1024) {
        ((float4*)ob)[t] = make_float4(0.f, 0.f, 0.f, 0.f);
        os[t] = 0.0f;
        ol[t] = 0.0f;
    }
    if (tid < 32) keepw[tid] = 0u;

    int   src = 0, lb = 0;
    float sc  = 0.0f;
    if (tid < TOPK) {
        unsigned int idx = ~(unsigned int)(r & 0xFFFFFFFFull);
        src = b * NANCH + (int)idx;
        lb  = g_label[src];
        sc  = funmap((unsigned int)(r >> 32));    // exact round-trip
        float4 bx = ((const float4*)g_box)[src];
        float off = (float)lb * MAX_WH;
        float a0 = bx.x + off, a1 = bx.y + off, a2 = bx.z + off, a3 = bx.w + off;
        nx1[tid] = a0; ny1[tid] = a1; nx2[tid] = a2; ny2[tid] = a3;
        nar[tid] = (a2 - a0) * (a3 - a1);
        slab[tid] = (unsigned char)lb;
    } else {
        slab[tid] = 0xFF;
    }
    __syncthreads();

    const float HI = 0.7000007f;
    const float LO = 0.6999993f;

    for (int l = wid; l < NCLS; l += 32) {
        int cnt = 0;
#pragma unroll 1
        for (int c = 0; c < 32; ++c) {
            int rank = c * 32 + lane;
            bool m = (slab[rank] == (unsigned char)l);
            unsigned bal = __ballot_sync(FULL, m);
            if (m) {
                int pos = cnt + __popc(bal & lmask);
                if (pos < GCAP) list[l * GCAP + pos] = (unsigned short)rank;
            }
            cnt += __popc(bal);
        }
        int g = min(cnt, GCAP);

        unsigned long long kept0 = 0ull, kept1 = 0ull;
#pragma unroll 1
        for (int m = 0; m < g; ++m) {
            int rm = list[l * GCAP + m];
            float cx1 = nx1[rm], cy1 = ny1[rm], cx2 = nx2[rm], cy2 = ny2[rm];
            float ca  = nar[rm];
            bool sup = false;
#pragma unroll 1
            for (int base = 0; base < m; base += 32) {
                int mi = base + lane;
                bool valid = (mi < m) &&
                    (((mi < 64) ? (kept0 >> mi) : (kept1 >> (mi - 64))) & 1ull);
                bool s = false;
                if (valid) {
                    int ri = list[l * GCAP + mi];
                    float lx = fmaxf(nx1[ri], cx1);
                    float ly = fmaxf(ny1[ri], cy1);
                    float rx = fminf(nx2[ri], cx2);
                    float ry = fminf(ny2[ri], cy2);
                    float wd = fmaxf(rx - lx, 0.0f);
                    float ht = fmaxf(ry - ly, 0.0f);
                    float inter = wd * ht;
                    float denom = nar[ri] + ca - inter + 1e-7f;
                    if (inter > HI * denom)       s = true;
                    else if (inter >= LO * denom) s = (inter / denom) > IOU_THR;
                }
                if (__ballot_sync(FULL, s)) { sup = true; break; }
            }
            if (!sup) {
                if (m < 64) kept0 |= 1ull << m; else kept1 |= 1ull << (m - 64);
                if (lane == 0) atomicOr(&keepw[rm >> 5], 1u << (rm & 31));
            }
        }
    }
    __syncthreads();

    // conf gate + block scan + scatter (kept are already score-descending)
    int f = 0;
    if (tid < TOPK)
        f = (int)((keepw[tid >> 5] >> (tid & 31)) & 1u) & (sc > CONF ? 1 : 0);
    unsigned bal = __ballot_sync(FULL, f);
    if (lane == 0) wtot[wid] = __popc(bal);
    __syncthreads();
    if (tid == 0) {
        int acc = 0;
        for (int i = 0; i < 32; i++) { woff[i] = acc; acc += wtot[i]; }
    }
    __syncthreads();
    int pos = woff[wid] + __popc(bal & lmask);

    if (f && pos < MAXDET) {
        ((float4*)ob)[pos] = ((const float4*)g_box)[src];
        os[pos] = sc;
        ol[pos] = (float)c_coco[lb];
    }
}

// ---------------- launch ----------------------------------------------------
extern "C" void kernel_launch(void* const* d_in, const int* in_sizes, int n_in,
                              void* d_out, int out_size) {
    (void)in_sizes; (void)n_in; (void)out_size;
    const float4* preds4 = (const float4*)d_in[0];
    float* out = (float*)d_out;

    cudaFuncSetAttribute(fused_kernel,
                         cudaFuncAttributeMaxDynamicSharedMemorySize, SEL_SMEM);

    dim3 dgrid((NQUAD * 2 + 255) / 256, NB);
    decode_kernel<<<dgrid, 256>>>(preds4);
    fused_kernel<<<NB, 1024, SEL_SMEM>>>(out);
}

// round 10
// speedup vs baseline: 1.9630x; 1.0648x over previous
#include <cuda_runtime.h>
#include <cstdint>

#define NB      32
#define NCH     84
#define NCLS    80
#define NANCH   8400
#define NQUAD   2100          // NANCH / 4
#define TOPK    1000
#define MAXDET  300
#define GCAP    128           // per-label member list capacity (4 lane-blocks)
#define CONF    0.25f
#define IOU_THR 0.7f
#define MAX_WH  7680.0f
#define IMG_SZ  640.0f

// ---------------- scratch (device globals; no allocation allowed) ----------
__device__ unsigned long long g_key  [NB * NANCH];   // (fmap(score)<<32)|~idx
__device__ int                g_label[NB * NANCH];
__device__ float              g_box  [NB * NANCH * 4];

__constant__ int c_coco[80] = {
    1,2,3,4,5,6,7,8,9,10,11,13,14,15,16,17,18,19,20,21,22,23,24,25,27,28,
    31,32,33,34,35,36,37,38,39,40,41,42,43,44,46,47,48,49,50,51,52,53,54,55,
    56,57,58,59,60,61,62,63,64,65,67,70,72,73,74,75,76,77,78,79,80,81,82,84,
    85,86,87,88,89,90
};

__device__ __forceinline__ unsigned int fmap(float f) {
    unsigned int u = __float_as_uint(f);
    return (u & 0x80000000u) ? ~u : (u | 0x80000000u);
}
__device__ __forceinline__ float funmap(unsigned int u) {
    return (u & 0x80000000u) ? __uint_as_float(u ^ 0x80000000u)
                             : __uint_as_float(~u);
}

// ---------------- stage 1: decode (channel-split pairs, float4 quads) ------
__global__ void __launch_bounds__(256) decode_kernel(const float4* __restrict__ p4) {
    int t = blockIdx.x * blockDim.x + threadIdx.x;
    int pair = t >> 1;
    int half = t & 1;
    int b = blockIdx.y;
    bool valid = (pair < NQUAD);
    int g = valid ? pair : (NQUAD - 1);
    const float4* base = p4 + (size_t)b * (NCH * NQUAD) + g;
    const float4* cb   = base + (size_t)(4 + (half ? 40 : 0)) * NQUAD;

    float4 vx = base[0];
    float4 vy = base[NQUAD];
    float4 vw = base[2 * NQUAD];
    float4 vh = base[3 * NQUAD];

    float4 best = cb[0];
    int4   bi   = make_int4(0, 0, 0, 0);
#pragma unroll
    for (int c = 1; c < 40; c++) {
        float4 v = cb[(size_t)c * NQUAD];
        if (v.x > best.x) { best.x = v.x; bi.x = c; }
        if (v.y > best.y) { best.y = v.y; bi.y = c; }
        if (v.z > best.z) { best.z = v.z; bi.z = c; }
        if (v.w > best.w) { best.w = v.w; bi.w = c; }
    }

    const unsigned FULL = 0xFFFFFFFFu;
    float obx = __shfl_down_sync(FULL, best.x, 1);
    float oby = __shfl_down_sync(FULL, best.y, 1);
    float obz = __shfl_down_sync(FULL, best.z, 1);
    float obw = __shfl_down_sync(FULL, best.w, 1);
    int   oix = __shfl_down_sync(FULL, bi.x, 1);
    int   oiy = __shfl_down_sync(FULL, bi.y, 1);
    int   oiz = __shfl_down_sync(FULL, bi.z, 1);
    int   oiw = __shfl_down_sync(FULL, bi.w, 1);

    if (half == 0 && valid) {
        if (obx > best.x) { best.x = obx; bi.x = oix + 40; }
        if (oby > best.y) { best.y = oby; bi.y = oiy + 40; }
        if (obz > best.z) { best.z = obz; bi.z = oiz + 40; }
        if (obw > best.w) { best.w = obw; bi.w = oiw + 40; }

        int o = b * NANCH + 4 * g;

        float s0 = (best.x > CONF) ? best.x : -1.0f;
        float s1 = (best.y > CONF) ? best.y : -1.0f;
        float s2 = (best.z > CONF) ? best.z : -1.0f;
        float s3 = (best.w > CONF) ? best.w : -1.0f;

        unsigned long long k0 = ((unsigned long long)fmap(s0) << 32) | (unsigned int)(~(4*g+0));
        unsigned long long k1 = ((unsigned long long)fmap(s1) << 32) | (unsigned int)(~(4*g+1));
        unsigned long long k2 = ((unsigned long long)fmap(s2) << 32) | (unsigned int)(~(4*g+2));
        unsigned long long k3 = ((unsigned long long)fmap(s3) << 32) | (unsigned int)(~(4*g+3));
        ((ulonglong2*)g_key)[o/2]     = make_ulonglong2(k0, k1);
        ((ulonglong2*)g_key)[o/2 + 1] = make_ulonglong2(k2, k3);

        ((int4*)g_label)[b * NQUAD + g] = bi;

        float4* boxo = (float4*)g_box + o;
        {
            float x = vx.x * IMG_SZ, y = vy.x * IMG_SZ, hw = vw.x * IMG_SZ * 0.5f, hh = vh.x * IMG_SZ * 0.5f;
            boxo[0] = make_float4(x - hw, y - hh, x + hw, y + hh);
        }
        {
            float x = vx.y * IMG_SZ, y = vy.y * IMG_SZ, hw = vw.y * IMG_SZ * 0.5f, hh = vh.y * IMG_SZ * 0.5f;
            boxo[1] = make_float4(x - hw, y - hh, x + hw, y + hh);
        }
        {
            float x = vx.z * IMG_SZ, y = vy.z * IMG_SZ, hw = vw.z * IMG_SZ * 0.5f, hh = vh.z * IMG_SZ * 0.5f;
            boxo[2] = make_float4(x - hw, y - hh, x + hw, y + hh);
        }
        {
            float x = vx.w * IMG_SZ, y = vy.w * IMG_SZ, hw = vw.w * IMG_SZ * 0.5f, hh = vh.w * IMG_SZ * 0.5f;
            boxo[3] = make_float4(x - hw, y - hh, x + hw, y + hh);
        }
    }
}

// ---------------- stage 2: fused wide-digit select + NMS + emit -------------
// Radix passes: 11 bits [63:53], 11 bits [52:42] (then compact active + gather
// sure winners), 10 bits [41:32] (splice known 0xFFFF idx-high bits), 8 bits
// [15:8], 8 bits [7:0]. Exactly TOPK keys >= final 64-bit prefix. Register
// bitonic sort gives global score order. NMS: atomic placement into per-label
// lists, in-place O(g^2) rank sort (ranks unique), per-warp greedy (cross-
// label suppression impossible with class-offset boxes), compact, emit.
#define SEL_SMEM ((8448 + 8448 + 1024) * 8)

__global__ void __launch_bounds__(1024) fused_kernel(float* __restrict__ out) {
    extern __shared__ unsigned long long sm[];
    unsigned long long* key  = sm;            // 8400 (8448 pad); dead after compaction
    unsigned long long* actl = sm + 8448;     // active set; dead after final gather
    unsigned long long* cand = sm + 16896;    // 1024 winners

    // phase-B aliases over dead regions
    unsigned short* list = (unsigned short*)key;            // [NCLS][GCAP] = 20KB
    float*          nx1  = (float*)actl;
    float*          ny1  = nx1 + TOPK;
    float*          nx2  = ny1 + TOPK;
    float*          ny2  = nx2 + TOPK;
    float*          nar  = ny2 + TOPK;

    __shared__ int hist[4][2048];
    __shared__ int hfin[2048];
    __shared__ unsigned long long s_prefix;
    __shared__ int s_k, s_cnt, s_actn;
    __shared__ int cnt[NCLS];
    __shared__ unsigned int keepw[32];
    __shared__ int wtot[32], woff[32];

    int b = blockIdx.x, tid = threadIdx.x;
    int wid = tid >> 5, lane = tid & 31;
    const unsigned FULL = 0xFFFFFFFFu;
    unsigned lmask = (1u << lane) - 1u;

    float* ob = out + (size_t)b * MAXDET * 4;
    float* os = out + (size_t)NB * MAXDET * 4 + (size_t)b * MAXDET;
    float* ol = out + (size_t)NB * MAXDET * 5 + (size_t)b * MAXDET;

    for (int i = tid; i < NANCH; i += 1024)
        key[i] = g_key[b * NANCH + i];
    if (tid == 0) { s_prefix = 0ull; s_k = TOPK; s_cnt = 0; s_actn = 0; }
    __syncthreads();

    const int WD[5]  = {11, 11, 10, 8, 8};   // digit widths
    const int SH[5]  = {53, 42, 32, 8, 0};   // digit shifts
    const int FS[5]  = { 0, 53, 42, 16, 8};  // filter shifts (pass 0 unfiltered)

#pragma unroll 1
    for (int pass = 0; pass < 5; ++pass) {
        int nb = 1 << WD[pass];
        // zero ALL 4 replicas every pass (replicas live at fixed 2048 strides;
        // partial zeroing left stale counts and broke the TOPK invariant)
        for (int i = tid; i < 4 * 2048; i += 1024) ((int*)hist)[i] = 0;
        __syncthreads();

        unsigned long long pfx = s_prefix;
        int shift = SH[pass], fs = FS[pass];
        unsigned mask = (unsigned)(nb - 1);
        const unsigned long long* arr = (pass < 2) ? key : actl;
        int n = (pass < 2) ? NANCH : s_actn;
        int iters = (n + 1023) >> 10;
        int sub = wid & 3;

#pragma unroll 1
        for (int ii = 0; ii < iters; ++ii) {
            int i = tid + (ii << 10);
            unsigned long long v = (i < n) ? arr[i] : 0ull;
            bool a = (i < n) && ((pass == 0) || ((v >> fs) == pfx));
            int bin = (int)((unsigned)(v >> shift) & mask);
            unsigned am = __ballot_sync(FULL, a);
            if (am == FULL) {
                int b0 = __shfl_sync(FULL, bin, 0);
                if (__all_sync(FULL, bin == b0)) {          // uniform fast path
                    if (lane == 0) atomicAdd(&hist[sub][b0], 32);
                    continue;
                }
            }
            if (a) atomicAdd(&hist[sub][bin], 1);
        }
        __syncthreads();

        for (int bb = tid; bb < nb; bb += 1024)
            hfin[bb] = hist[0][bb] + hist[1][bb] + hist[2][bb] + hist[3][bb];
        __syncthreads();

        // warp 0: suffix scan over lanes, walk down within the selected lane
        if (tid < 32) {
            int bpl = nb >> 5;
            int base = lane * bpl;
            int tot = 0;
            for (int e = 0; e < bpl; ++e) tot += hfin[base + e];
            int suf = tot;
#pragma unroll
            for (int o = 1; o < 32; o <<= 1) {
                int v2 = __shfl_down_sync(FULL, suf, o);
                if (lane + o < 32) suf += v2;
            }
            int S = suf - tot;                 // strict suffix (higher lanes)
            int k = s_k;
            if (k > S && k <= S + tot) {
                int S2 = S;
                for (int e = bpl - 1; e >= 0; --e) {
                    int h = hfin[base + e];
                    if (k <= S2 + h) {
                        unsigned long long np =
                            (s_prefix << WD[pass]) | (unsigned long long)(base + e);
                        if (pass == 2) np = (np << 16) | 0xFFFFull;  // ~idx high bits
                        s_prefix = np;
                        s_k = k - S2;
                        break;
                    }
                    S2 += h;
                }
            }
        }
        __syncthreads();

        // after pass 1 (22-bit prefix): compact active + gather sure winners
        if (pass == 1) {
            unsigned long long p22 = s_prefix;
#pragma unroll 1
            for (int ii = 0; ii < 9; ++ii) {
                int i = tid + (ii << 10);
                unsigned long long v = (i < NANCH) ? key[i] : 0ull;
                unsigned long long hi = v >> 42;
                bool m  = (i < NANCH) && (hi == p22);
                bool sw = (i < NANCH) && (hi > p22);
                unsigned balm = __ballot_sync(FULL, m);
                if (balm) {
                    int base2 = 0;
                    if (lane == 0) base2 = atomicAdd(&s_actn, __popc(balm));
                    base2 = __shfl_sync(FULL, base2, 0);
                    if (m) actl[base2 + __popc(balm & lmask)] = v;
                }
                unsigned balw = __ballot_sync(FULL, sw);
                if (balw) {
                    int base2 = 0;
                    if (lane == 0) base2 = atomicAdd(&s_cnt, __popc(balw));
                    base2 = __shfl_sync(FULL, base2, 0);
                    if (sw) cand[base2 + __popc(balw & lmask)] = v;
                }
            }
            __syncthreads();
        }
    }

    // final winners from the active set: exactly TOPK - s_cnt keys >= thr
    {
        unsigned long long thr = s_prefix;
        int n2 = s_actn;
        int iters = (n2 + 1023) >> 10;
#pragma unroll 1
        for (int ii = 0; ii < iters; ++ii) {
            int i = tid + (ii << 10);
            unsigned long long v = (i < n2) ? actl[i] : 0ull;
            bool win = (i < n2) && (v >= thr);
            unsigned bal = __ballot_sync(FULL, win);
            if (bal) {
                int base2 = 0;
                if (lane == 0) base2 = atomicAdd(&s_cnt, __popc(bal));
                base2 = __shfl_sync(FULL, base2, 0);
                if (win) cand[base2 + __popc(bal & lmask)] = v;
            }
        }
    }
    __syncthreads();
    if (tid < 1024 - TOPK) cand[TOPK + tid] = 0ull;
    __syncthreads();

    // register bitonic sort, descending
    unsigned long long r = (tid < TOPK) ? cand[tid] : 0ull;
#pragma unroll 1
    for (int kk = 2; kk <= 1024; kk <<= 1) {
#pragma unroll 1
        for (int j = kk >> 1; j > 0; j >>= 1) {
            unsigned long long o;
            if (j >= 32) {
                __syncthreads();
                cand[tid] = r;
                __syncthreads();
                o = cand[tid ^ j];
            } else {
                o = __shfl_xor_sync(FULL, r, j);
            }
            bool up    = ((tid & kk) == 0);
            bool lower = ((tid & j) == 0);
            unsigned long long mx = (r > o) ? r : o;
            unsigned long long mn = (r > o) ? o : r;
            r = (up == lower) ? mx : mn;
        }
    }

    // ---------------- phase B: gather + per-label NMS + emit ----------------
    for (int t = tid; t < MAXDET; t += 1024) {
        ((float4*)ob)[t] = make_float4(0.f, 0.f, 0.f, 0.f);
        os[t] = 0.0f;
        ol[t] = 0.0f;
    }
    if (tid < 32) keepw[tid] = 0u;
    if (tid < NCLS) cnt[tid] = 0;

    int   src = 0, lb = 0;
    float sc  = 0.0f;
    if (tid < TOPK) {
        unsigned int idx = ~(unsigned int)(r & 0xFFFFFFFFull);
        src = b * NANCH + (int)idx;
        lb  = g_label[src];
        sc  = funmap((unsigned int)(r >> 32));
        float4 bx = ((const float4*)g_box)[src];
        float off = (float)lb * MAX_WH;
        float a0 = bx.x + off, a1 = bx.y + off, a2 = bx.z + off, a3 = bx.w + off;
        nx1[tid] = a0; ny1[tid] = a1; nx2[tid] = a2; ny2[tid] = a3;
        nar[tid] = (a2 - a0) * (a3 - a1);
    }
    __syncthreads();

    // unordered placement into per-label lists (ranks = tid, unique)
    if (tid < TOPK) {
        int p = atomicAdd(&cnt[lb], 1);
        if (p < GCAP) list[lb * GCAP + p] = (unsigned short)tid;
    }
    __syncthreads();

    const float HI = 0.7000007f;
    const float LO = 0.6999993f;

    for (int l = wid; l < NCLS; l += 32) {
        int g = min(cnt[l], GCAP);
        int base = l * GCAP;

        // in-place rank sort: position = count of smaller ranks (all unique)
        int rr[GCAP / 32], pp[GCAP / 32];
#pragma unroll
        for (int blk = 0; blk < GCAP / 32; ++blk) {
            int i = blk * 32 + lane;
            int ri = 0, c = 0;
            if (i < g) {
                ri = list[base + i];
                for (int j = 0; j < g; ++j) c += (list[base + j] < ri) ? 1 : 0;
            }
            rr[blk] = ri; pp[blk] = c;
        }
        __syncwarp();
#pragma unroll
        for (int blk = 0; blk < GCAP / 32; ++blk) {
            int i = blk * 32 + lane;
            if (i < g) list[base + pp[blk]] = (unsigned short)rr[blk];
        }
        __syncwarp();

        // greedy: serial over members (score-desc), lanes over earlier kept
        unsigned long long kept0 = 0ull, kept1 = 0ull;
#pragma unroll 1
        for (int m = 0; m < g; ++m) {
            int rm = list[base + m];
            float cx1 = nx1[rm], cy1 = ny1[rm], cx2 = nx2[rm], cy2 = ny2[rm];
            float ca  = nar[rm];
            bool sup = false;
#pragma unroll 1
            for (int bs = 0; bs < m; bs += 32) {
                int mi = bs + lane;
                bool valid = (mi < m) &&
                    (((mi < 64) ? (kept0 >> mi) : (kept1 >> (mi - 64))) & 1ull);
                bool s = false;
                if (valid) {
                    int ri = list[base + mi];
                    float lx = fmaxf(nx1[ri], cx1);
                    float ly = fmaxf(ny1[ri], cy1);
                    float rx = fminf(nx2[ri], cx2);
                    float ry = fminf(ny2[ri], cy2);
                    float wd = fmaxf(rx - lx, 0.0f);
                    float ht = fmaxf(ry - ly, 0.0f);
                    float inter = wd * ht;
                    float denom = nar[ri] + ca - inter + 1e-7f;
                    if (inter > HI * denom)       s = true;
                    else if (inter >= LO * denom) s = (inter / denom) > IOU_THR;
                }
                if (__ballot_sync(FULL, s)) { sup = true; break; }
            }
            if (!sup) {
                if (m < 64) kept0 |= 1ull << m; else kept1 |= 1ull << (m - 64);
                if (lane == 0) atomicOr(&keepw[rm >> 5], 1u << (rm & 31));
            }
        }
    }
    __syncthreads();

    // conf gate + block scan + scatter (kept are already score-descending)
    int f = 0;
    if (tid < TOPK)
        f = (int)((keepw[tid >> 5] >> (tid & 31)) & 1u) & (sc > CONF ? 1 : 0);
    unsigned bal = __ballot_sync(FULL, f);
    if (lane == 0) wtot[wid] = __popc(bal);
    __syncthreads();
    if (tid == 0) {
        int acc = 0;
        for (int i = 0; i < 32; i++) { woff[i] = acc; acc += wtot[i]; }
    }
    __syncthreads();
    int pos = woff[wid] + __popc(bal & lmask);

    if (f && pos < MAXDET) {
        ((float4*)ob)[pos] = ((const float4*)g_box)[src];
        os[pos] = sc;
        ol[pos] = (float)c_coco[lb];
    }
}

// ---------------- launch ----------------------------------------------------
extern "C" void kernel_launch(void* const* d_in, const int* in_sizes, int n_in,
                              void* d_out, int out_size) {
    (void)in_sizes; (void)n_in; (void)out_size;
    const float4* preds4 = (const float4*)d_in[0];
    float* out = (float*)d_out;

    cudaFuncSetAttribute(fused_kernel,
                         cudaFuncAttributeMaxDynamicSharedMemorySize, SEL_SMEM);

    dim3 dgrid((NQUAD * 2 + 255) / 256, NB);
    decode_kernel<<<dgrid, 256>>>(preds4);
    fused_kernel<<<NB, 1024, SEL_SMEM>>>(out);
}